// round 15
// baseline (speedup 1.0000x reference)
#include <cuda_runtime.h>
#include <cuda_fp16.h>
#include <cstdint>

#define DIM     512
#define HEADS   8
#define DH      64
#define BATCH   8
#define NWIN    64
#define WSZ     64
#define NTOK    (BATCH * NWIN * WSZ)   // 32768

// Scratch (allocation-free rule: __device__ globals)
__device__ __half g_xh[(size_t)NTOK * DIM];                       // 33.5 MB
__device__ __half g_qkvh[(size_t)NTOK * 3 * DIM];                 // 100 MB
__device__ __half g_attnh[(size_t)NTOK * DIM];                    // 33.5 MB
__device__ __half g_wth[(size_t)(3 * DIM) * DIM + DIM * DIM];     // 2 MB (wqkvT, wprojT)

// ---------------------------------------------------------------------------
// helpers
// ---------------------------------------------------------------------------
__device__ __forceinline__ uint32_t smem_u32(const void* p) {
    uint32_t a;
    asm("{ .reg .u64 t; cvta.to.shared.u64 t, %1; cvt.u32.u64 %0, t; }"
        : "=r"(a) : "l"(p));
    return a;
}

__device__ __forceinline__ void cp16(uint32_t dst, const void* src) {
    asm volatile("cp.async.cg.shared.global [%0], [%1], 16;"
                 :: "r"(dst), "l"(src) : "memory");
}

__device__ __forceinline__ void ldsm4(unsigned r[4], uint32_t a) {
    asm volatile("ldmatrix.sync.aligned.m8n8.x4.shared.b16 {%0,%1,%2,%3}, [%4];"
                 : "=r"(r[0]), "=r"(r[1]), "=r"(r[2]), "=r"(r[3]) : "r"(a));
}

__device__ __forceinline__ void ldsm4t(unsigned r[4], uint32_t a) {
    asm volatile("ldmatrix.sync.aligned.m8n8.x4.trans.shared.b16 {%0,%1,%2,%3}, [%4];"
                 : "=r"(r[0]), "=r"(r[1]), "=r"(r[2]), "=r"(r[3]) : "r"(a));
}

__device__ __forceinline__ void mma_f16(float c[4], const unsigned a[4],
                                        const unsigned b[2]) {
    asm volatile(
        "mma.sync.aligned.m16n8k16.row.col.f32.f16.f16.f32 "
        "{%0,%1,%2,%3}, {%4,%5,%6,%7}, {%8,%9}, {%0,%1,%2,%3};"
        : "+f"(c[0]), "+f"(c[1]), "+f"(c[2]), "+f"(c[3])
        : "r"(a[0]), "r"(a[1]), "r"(a[2]), "r"(a[3]), "r"(b[0]), "r"(b[1]));
}

// ---------------------------------------------------------------------------
// Fused prologue (one launch):
//  blocks [0, 16384): x fp32 -> fp16
//  blocks [16384, 17152): transpose+convert w_qkv [512,1536] -> [1536,512] half
//  blocks [17152, 17408): transpose+convert w_proj [512,512] -> [512,512] half
// ---------------------------------------------------------------------------
__global__ __launch_bounds__(256) void prologue_k(
    const float* __restrict__ x, __half* __restrict__ xh,
    const float* __restrict__ w_qkv, __half* __restrict__ wqkvT,
    const float* __restrict__ w_proj, __half* __restrict__ wprojT)
{
    __shared__ float t[32][33];
    const int blk = blockIdx.x;
    const int tid = threadIdx.x;

    if (blk < 16384) {
        const int i = blk * 256 + tid;          // < NTOK*DIM/4
        float4 v = ((const float4*)x)[i];
        __half2* o = (__half2*)(xh + (size_t)i * 4);
        o[0] = __floats2half2_rn(v.x, v.y);
        o[1] = __floats2half2_rn(v.z, v.w);
        return;
    }

    const float* in;
    __half* outp;
    int C, bx, by;
    if (blk < 16384 + 768) {
        in = w_qkv; outp = wqkvT; C = 1536;
        const int bb = blk - 16384;
        bx = bb % 48; by = bb / 48;
    } else {
        in = w_proj; outp = wprojT; C = 512;
        const int bb = blk - 17152;
        bx = bb % 16; by = bb / 16;
    }
    const int R = 512;
    const int tx = tid & 31, ty = tid >> 5;     // 32 x 8
    #pragma unroll
    for (int j = 0; j < 32; j += 8)
        t[ty + j][tx] = in[(size_t)(by * 32 + ty + j) * C + bx * 32 + tx];
    __syncthreads();
    #pragma unroll
    for (int j = 0; j < 32; j += 8)
        outp[(size_t)(bx * 32 + ty + j) * R + by * 32 + tx] =
            __float2half_rn(t[tx][ty + j]);
}

// ---------------------------------------------------------------------------
// fp16 GEMM (R8 tile config + interleaved LDSM/HMMA): C = A @ Bt^T (+bias).
// 128x128 tile, BK=64, 3-stage cp.async, 256 thr / 8 warps (4m x 2n),
// warp tile 32x64. B-pair fragments rotate through a 2-deep buffer so each
// ldmatrix issues between the mmas consuming the previous pair (asm volatile
// order is preserved by the compiler, so this IS the issue order).
// ---------------------------------------------------------------------------
#define ST_H      72
#define TILE_H    (128 * ST_H)
#define NSTAGE    3
#define GEMM_SMEM (NSTAGE * 2 * TILE_H * 2)    // 110592 bytes

__global__ __launch_bounds__(256, 2) void gemm_h(
    const __half* __restrict__ A, const __half* __restrict__ Bt,
    const float* __restrict__ bias, void* __restrict__ Cout,
    int M, int N, int K, int out_half)
{
    extern __shared__ __align__(16) __half smh[];
    __half* As = smh;                       // [3][128][72]
    __half* Bs = smh + NSTAGE * TILE_H;     // [3][128][72]
    const uint32_t as_a = smem_u32(As);
    const uint32_t bs_a = smem_u32(Bs);

    const int tid  = threadIdx.x;
    const int lane = tid & 31;
    const int wid  = tid >> 5;
    const int wm   = (wid & 3) * 32;
    const int wn   = (wid >> 2) * 64;
    const int bm   = blockIdx.y * 128;
    const int bn   = blockIdx.x * 128;
    const int q    = lane & 3;
    const int g    = lane >> 2;

    const int m8  = lane & 7;
    const int sel = lane >> 3;
    uint32_t a_off[2], b_off[4];
    #pragma unroll
    for (int mt = 0; mt < 2; mt++)
        a_off[mt] = (uint32_t)(((wm + mt * 16 + ((sel & 1) << 3) + m8) * ST_H
                                + ((sel >> 1) << 3)) * 2);
    #pragma unroll
    for (int p = 0; p < 4; p++)
        b_off[p] = (uint32_t)(((wn + ((p << 1) + (sel >> 1)) * 8 + m8) * ST_H
                               + ((sel & 1) << 3)) * 2);

    float acc[2][8][4];
    #pragma unroll
    for (int i = 0; i < 2; i++)
        #pragma unroll
        for (int j = 0; j < 8; j++)
            #pragma unroll
            for (int k = 0; k < 4; k++) acc[i][j][k] = 0.f;

    const int NT = K >> 6;

    #define LOAD_STAGE(kt_)                                                     \
    do {                                                                        \
        const int s_  = (kt_) % NSTAGE;                                         \
        const int k0_ = (kt_) * 64;                                             \
        _Pragma("unroll")                                                       \
        for (int i_ = 0; i_ < 2; i_++) {                                        \
            const int idx_ = tid + i_ * 256;                                    \
            const int row_ = idx_ >> 2;                                         \
            const int c_   = (idx_ & 3) * 16;                                   \
            cp16(as_a + (uint32_t)(s_ * TILE_H + row_ * ST_H + c_) * 2,         \
                 A + (size_t)(bm + row_) * K + k0_ + c_);                       \
            cp16(as_a + (uint32_t)(s_ * TILE_H + row_ * ST_H + c_ + 8) * 2,     \
                 A + (size_t)(bm + row_) * K + k0_ + c_ + 8);                   \
            cp16(bs_a + (uint32_t)(s_ * TILE_H + row_ * ST_H + c_) * 2,         \
                 Bt + (size_t)(bn + row_) * K + k0_ + c_);                      \
            cp16(bs_a + (uint32_t)(s_ * TILE_H + row_ * ST_H + c_ + 8) * 2,     \
                 Bt + (size_t)(bn + row_) * K + k0_ + c_ + 8);                  \
        }                                                                       \
        asm volatile("cp.async.commit_group;" ::: "memory");                    \
    } while (0)

    LOAD_STAGE(0);
    LOAD_STAGE(1);

    for (int kt = 0; kt < NT; kt++) {
        if (kt < NT - 1)
            asm volatile("cp.async.wait_group 1;" ::: "memory");
        else
            asm volatile("cp.async.wait_group 0;" ::: "memory");
        __syncthreads();
        if (kt + 2 < NT) LOAD_STAGE(kt + 2);

        const int st = kt % NSTAGE;
        const uint32_t sa = as_a + (uint32_t)(st * TILE_H) * 2;
        const uint32_t sb = bs_a + (uint32_t)(st * TILE_H) * 2;

        #pragma unroll
        for (int ks = 0; ks < 4; ks++) {
            const uint32_t ko = (uint32_t)(ks * 32);
            unsigned afr[2][4];
            unsigned bb[2][4];                    // rotating B-pair buffer
            ldsm4(afr[0], sa + a_off[0] + ko);
            ldsm4(afr[1], sa + a_off[1] + ko);
            ldsm4(bb[0], sb + b_off[0] + ko);
            #pragma unroll
            for (int p = 0; p < 4; p++) {
                if (p < 3)
                    ldsm4(bb[(p + 1) & 1], sb + b_off[p + 1] + ko);
                const unsigned* t = bb[p & 1];
                unsigned b0[2] = {t[0], t[1]};
                unsigned b1[2] = {t[2], t[3]};
                mma_f16(acc[0][2 * p],     afr[0], b0);
                mma_f16(acc[0][2 * p + 1], afr[0], b1);
                mma_f16(acc[1][2 * p],     afr[1], b0);
                mma_f16(acc[1][2 * p + 1], afr[1], b1);
            }
        }
    }

    if (out_half) {
        __half* Ch = (__half*)Cout;
        #pragma unroll
        for (int nt = 0; nt < 8; nt++) {
            const int col = bn + wn + nt * 8 + 2 * q;
            #pragma unroll
            for (int mt = 0; mt < 2; mt++) {
                const int r0 = bm + wm + mt * 16 + g;
                *(__half2*)(Ch + (size_t)r0 * N + col) =
                    __floats2half2_rn(acc[mt][nt][0], acc[mt][nt][1]);
                *(__half2*)(Ch + (size_t)(r0 + 8) * N + col) =
                    __floats2half2_rn(acc[mt][nt][2], acc[mt][nt][3]);
            }
        }
    } else {
        float* Cf = (float*)Cout;
        #pragma unroll
        for (int nt = 0; nt < 8; nt++) {
            const int col = bn + wn + nt * 8 + 2 * q;
            float b0 = 0.f, b1 = 0.f;
            if (bias) { b0 = bias[col]; b1 = bias[col + 1]; }
            #pragma unroll
            for (int mt = 0; mt < 2; mt++) {
                const int r0 = bm + wm + mt * 16 + g;
                *(float2*)(Cf + (size_t)r0 * N + col) =
                    make_float2(acc[mt][nt][0] + b0, acc[mt][nt][1] + b1);
                *(float2*)(Cf + (size_t)(r0 + 8) * N + col) =
                    make_float2(acc[mt][nt][2] + b0, acc[mt][nt][3] + b1);
            }
        }
    }
    #undef LOAD_STAGE
}

// ---------------------------------------------------------------------------
// Window attention: fp16 mma, TWO windows per 256-thread block (8 warps).
// Warp wid: sub = wid>>2 selects window, w4 = wid&3 owns rows 16*w4..16*w4+15.
// (R14 champion, unchanged)
// ---------------------------------------------------------------------------
#define AST 72

__global__ __launch_bounds__(256) void window_attn_h(
    const __half* __restrict__ qkv, __half* __restrict__ out)
{
    __shared__ __half Qh[2][64][AST];    // Q, then P
    __shared__ __half KVh[2][64][AST];   // K, then V

    const int tid  = threadIdx.x;
    const int lane = tid & 31;
    const int wid  = tid >> 5;          // 0..7
    const int sub  = wid >> 2;          // window within pair
    const int w4   = wid & 3;           // row quarter
    const int g    = lane >> 2;
    const int q    = lane & 3;
    const int m8   = lane & 7;
    const int sel  = lane >> 3;

    const int base = blockIdx.x * 2;    // first window index
    const int n0   = base & 63;
    const int h    = (base >> 6) & 7;
    const int b    = base >> 9;

    // Load Q,K of both windows into smem; prefetch V to registers.
    uint4 vpre[4];
    #pragma unroll
    for (int i = 0; i < 4; i++) {
        const int pos = i * 256 + tid;      // 0..1023
        const int win = pos >> 9;           // 0/1
        const int rc  = pos & 511;
        const int row = rc >> 3;            // 0..63
        const int c8  = (rc & 7) * 8;       // halves 0..56
        const size_t tokbase =
            ((size_t)(b * NWIN + n0 + win) * WSZ) * (3 * DIM);
        const __half* src = qkv + tokbase + (size_t)row * (3 * DIM) + h * DH + c8;
        *(uint4*)&Qh[win][row][c8]  = *(const uint4*)src;
        *(uint4*)&KVh[win][row][c8] = *(const uint4*)(src + DIM);
        vpre[i] = *(const uint4*)(src + 2 * DIM);
    }
    __syncthreads();

    const uint32_t qbase = smem_u32(&Qh[sub][0][0]);
    const uint32_t kbase = smem_u32(&KVh[sub][0][0]);

    const uint32_t aoff =
        (uint32_t)(((w4 * 16 + ((sel & 1) << 3) + m8) * AST + ((sel >> 1) << 3)) * 2);
    uint32_t boff[4], voff[4];
    #pragma unroll
    for (int p = 0; p < 4; p++) {
        boff[p] = (uint32_t)(((((p << 1) + (sel >> 1)) * 8 + m8) * AST
                              + ((sel & 1) << 3)) * 2);
        voff[p] = (uint32_t)(((((sel & 1) << 3) + m8) * AST
                              + ((p << 1) + (sel >> 1)) * 8) * 2);
    }

    // S = Q K^T
    float sacc[8][4];
    #pragma unroll
    for (int nt = 0; nt < 8; nt++)
        #pragma unroll
        for (int j = 0; j < 4; j++) sacc[nt][j] = 0.f;

    #pragma unroll
    for (int ks = 0; ks < 4; ks++) {
        const uint32_t ko = (uint32_t)(ks * 32);
        unsigned a[4], bfr[8][2];
        ldsm4(a, qbase + aoff + ko);
        #pragma unroll
        for (int p = 0; p < 4; p++) {
            unsigned t[4];
            ldsm4(t, kbase + boff[p] + ko);
            bfr[2 * p][0] = t[0]; bfr[2 * p][1] = t[1];
            bfr[2 * p + 1][0] = t[2]; bfr[2 * p + 1][1] = t[3];
        }
        #pragma unroll
        for (int nt = 0; nt < 8; nt++)
            mma_f16(sacc[nt], a, bfr[nt]);
    }

    // Register softmax (rows warp-private)
    const float scale = 0.125f;
    float mx0 = -1e30f, mx1 = -1e30f;
    #pragma unroll
    for (int nt = 0; nt < 8; nt++) {
        #pragma unroll
        for (int j = 0; j < 4; j++) sacc[nt][j] *= scale;
        mx0 = fmaxf(mx0, fmaxf(sacc[nt][0], sacc[nt][1]));
        mx1 = fmaxf(mx1, fmaxf(sacc[nt][2], sacc[nt][3]));
    }
    mx0 = fmaxf(mx0, __shfl_xor_sync(0xffffffffu, mx0, 1));
    mx0 = fmaxf(mx0, __shfl_xor_sync(0xffffffffu, mx0, 2));
    mx1 = fmaxf(mx1, __shfl_xor_sync(0xffffffffu, mx1, 1));
    mx1 = fmaxf(mx1, __shfl_xor_sync(0xffffffffu, mx1, 2));

    float s0 = 0.f, s1 = 0.f;
    #pragma unroll
    for (int nt = 0; nt < 8; nt++) {
        sacc[nt][0] = __expf(sacc[nt][0] - mx0);
        sacc[nt][1] = __expf(sacc[nt][1] - mx0);
        sacc[nt][2] = __expf(sacc[nt][2] - mx1);
        sacc[nt][3] = __expf(sacc[nt][3] - mx1);
        s0 += sacc[nt][0] + sacc[nt][1];
        s1 += sacc[nt][2] + sacc[nt][3];
    }
    s0 += __shfl_xor_sync(0xffffffffu, s0, 1);
    s0 += __shfl_xor_sync(0xffffffffu, s0, 2);
    s1 += __shfl_xor_sync(0xffffffffu, s1, 1);
    s1 += __shfl_xor_sync(0xffffffffu, s1, 2);
    const float inv0 = 1.f / s0, inv1 = 1.f / s1;

    // P -> Qh[sub] (warp-private rows)
    {
        const int r = w4 * 16 + g;
        #pragma unroll
        for (int nt = 0; nt < 8; nt++) {
            const int col = nt * 8 + 2 * q;
            *(__half2*)&Qh[sub][r][col] =
                __floats2half2_rn(sacc[nt][0] * inv0, sacc[nt][1] * inv0);
            *(__half2*)&Qh[sub][r + 8][col] =
                __floats2half2_rn(sacc[nt][2] * inv1, sacc[nt][3] * inv1);
        }
    }
    __syncthreads();

    // V -> KVh
    #pragma unroll
    for (int i = 0; i < 4; i++) {
        const int pos = i * 256 + tid;
        const int win = pos >> 9;
        const int rc  = pos & 511;
        const int row = rc >> 3;
        const int c8  = (rc & 7) * 8;
        *(uint4*)&KVh[win][row][c8] = vpre[i];
    }
    __syncthreads();

    // O = P V  (V via ldmatrix.trans)
    float oacc[8][4];
    #pragma unroll
    for (int nt = 0; nt < 8; nt++)
        #pragma unroll
        for (int j = 0; j < 4; j++) oacc[nt][j] = 0.f;

    #pragma unroll
    for (int ks = 0; ks < 4; ks++) {
        const uint32_t ko  = (uint32_t)(ks * 32);
        const uint32_t kov = (uint32_t)(ks * 16 * AST * 2);
        unsigned a[4], bfr[8][2];
        ldsm4(a, qbase + aoff + ko);
        #pragma unroll
        for (int p = 0; p < 4; p++) {
            unsigned t[4];
            ldsm4t(t, kbase + voff[p] + kov);
            bfr[2 * p][0] = t[0]; bfr[2 * p][1] = t[1];
            bfr[2 * p + 1][0] = t[2]; bfr[2 * p + 1][1] = t[3];
        }
        #pragma unroll
        for (int nt = 0; nt < 8; nt++)
            mma_f16(oacc[nt], a, bfr[nt]);
    }

    // O -> half, [B,H,NW,W,dh] linear layout
    const size_t obase =
        (((size_t)(b * HEADS + h) * NWIN + (n0 + sub)) * WSZ) * DH;
    const int r = w4 * 16 + g;
    #pragma unroll
    for (int nt = 0; nt < 8; nt++) {
        const int col = nt * 8 + 2 * q;
        *(__half2*)(out + obase + (size_t)r * DH + col) =
            __floats2half2_rn(oacc[nt][0], oacc[nt][1]);
        *(__half2*)(out + obase + (size_t)(r + 8) * DH + col) =
            __floats2half2_rn(oacc[nt][2], oacc[nt][3]);
    }
}

// ---------------------------------------------------------------------------
extern "C" void kernel_launch(void* const* d_in, const int* in_sizes, int n_in,
                              void* d_out, int out_size)
{
    const float* x      = (const float*)d_in[0];  // [8,64,64,512]
    const float* w_qkv  = (const float*)d_in[1];  // [512,1536]
    const float* w_proj = (const float*)d_in[2];  // [512,512]
    const float* b_proj = (const float*)d_in[3];  // [512]
    float* out = (float*)d_out;                   // [8,64,64,512]

    __half *xh, *qkvh, *attnh, *wth;
    cudaGetSymbolAddress((void**)&xh,    g_xh);
    cudaGetSymbolAddress((void**)&qkvh,  g_qkvh);
    cudaGetSymbolAddress((void**)&attnh, g_attnh);
    cudaGetSymbolAddress((void**)&wth,   g_wth);
    __half* wqkvT_h  = wth;                            // [1536,512]
    __half* wprojT_h = wth + (size_t)(3 * DIM) * DIM;  // [512,512]

    static bool attr_set = false;
    if (!attr_set) {
        cudaFuncSetAttribute(gemm_h,
                             cudaFuncAttributeMaxDynamicSharedMemorySize, GEMM_SMEM);
        attr_set = true;
    }

    // 0) fused prologue: x -> half; weights -> transposed half (one launch)
    prologue_k<<<16384 + 768 + 256, 256>>>(x, xh, w_qkv, wqkvT_h, w_proj, wprojT_h);

    // 1) qkv = x @ w_qkv (fp16 in, fp16 out)
    {
        dim3 grid((3 * DIM) / 128, NTOK / 128);
        gemm_h<<<grid, 256, GEMM_SMEM>>>(xh, wqkvT_h, nullptr, qkvh,
                                         NTOK, 3 * DIM, DIM, 1);
    }
    // 2) per-window attention (2 windows / block) -> [B,H,NW,W,dh] linear
    {
        window_attn_h<<<BATCH * HEADS * NWIN / 2, 256>>>(qkvh, attnh);
    }
    // 3) out = attn_flat @ w_proj + b_proj (fp16 in, fp32 out)
    {
        dim3 grid(DIM / 128, NTOK / 128);
        gemm_h<<<grid, 256, GEMM_SMEM>>>(attnh, wprojT_h, b_proj, out,
                                         NTOK, DIM, DIM, 0);
    }
}

// round 16
// speedup vs baseline: 1.0167x; 1.0167x over previous
#include <cuda_runtime.h>
#include <cuda_fp16.h>
#include <cstdint>

#define DIM     512
#define HEADS   8
#define DH      64
#define BATCH   8
#define NWIN    64
#define WSZ     64
#define NTOK    (BATCH * NWIN * WSZ)   // 32768

// Scratch (allocation-free rule: __device__ globals)
__device__ __half g_xh[(size_t)NTOK * DIM];                       // 33.5 MB
__device__ __half g_qkvh[(size_t)NTOK * 3 * DIM];                 // 100 MB
__device__ __half g_attnh[(size_t)NTOK * DIM];                    // 33.5 MB
__device__ __half g_wth[(size_t)(3 * DIM) * DIM + DIM * DIM];     // 2 MB (wqkvT, wprojT)

// ---------------------------------------------------------------------------
// helpers
// ---------------------------------------------------------------------------
__device__ __forceinline__ uint32_t smem_u32(const void* p) {
    uint32_t a;
    asm("{ .reg .u64 t; cvta.to.shared.u64 t, %1; cvt.u32.u64 %0, t; }"
        : "=r"(a) : "l"(p));
    return a;
}

__device__ __forceinline__ void cp16(uint32_t dst, const void* src) {
    asm volatile("cp.async.cg.shared.global [%0], [%1], 16;"
                 :: "r"(dst), "l"(src) : "memory");
}

__device__ __forceinline__ void ldsm4(unsigned r[4], uint32_t a) {
    asm volatile("ldmatrix.sync.aligned.m8n8.x4.shared.b16 {%0,%1,%2,%3}, [%4];"
                 : "=r"(r[0]), "=r"(r[1]), "=r"(r[2]), "=r"(r[3]) : "r"(a));
}

__device__ __forceinline__ void ldsm4t(unsigned r[4], uint32_t a) {
    asm volatile("ldmatrix.sync.aligned.m8n8.x4.trans.shared.b16 {%0,%1,%2,%3}, [%4];"
                 : "=r"(r[0]), "=r"(r[1]), "=r"(r[2]), "=r"(r[3]) : "r"(a));
}

__device__ __forceinline__ void mma_f16(float c[4], const unsigned a[4],
                                        const unsigned b[2]) {
    asm volatile(
        "mma.sync.aligned.m16n8k16.row.col.f32.f16.f16.f32 "
        "{%0,%1,%2,%3}, {%4,%5,%6,%7}, {%8,%9}, {%0,%1,%2,%3};"
        : "+f"(c[0]), "+f"(c[1]), "+f"(c[2]), "+f"(c[3])
        : "r"(a[0]), "r"(a[1]), "r"(a[2]), "r"(a[3]), "r"(b[0]), "r"(b[1]));
}

// ---------------------------------------------------------------------------
// Fused prologue (one launch):
//  blocks [0, 16384): x fp32 -> fp16
//  blocks [16384, 17152): transpose+convert w_qkv [512,1536] -> [1536,512] half
//  blocks [17152, 17408): transpose+convert w_proj [512,512] -> [512,512] half
// ---------------------------------------------------------------------------
__global__ __launch_bounds__(256) void prologue_k(
    const float* __restrict__ x, __half* __restrict__ xh,
    const float* __restrict__ w_qkv, __half* __restrict__ wqkvT,
    const float* __restrict__ w_proj, __half* __restrict__ wprojT)
{
    __shared__ float t[32][33];
    const int blk = blockIdx.x;
    const int tid = threadIdx.x;

    if (blk < 16384) {
        const int i = blk * 256 + tid;          // < NTOK*DIM/4
        float4 v = ((const float4*)x)[i];
        __half2* o = (__half2*)(xh + (size_t)i * 4);
        o[0] = __floats2half2_rn(v.x, v.y);
        o[1] = __floats2half2_rn(v.z, v.w);
        return;
    }

    const float* in;
    __half* outp;
    int C, bx, by;
    if (blk < 16384 + 768) {
        in = w_qkv; outp = wqkvT; C = 1536;
        const int bb = blk - 16384;
        bx = bb % 48; by = bb / 48;
    } else {
        in = w_proj; outp = wprojT; C = 512;
        const int bb = blk - 17152;
        bx = bb % 16; by = bb / 16;
    }
    const int R = 512;
    const int tx = tid & 31, ty = tid >> 5;     // 32 x 8
    #pragma unroll
    for (int j = 0; j < 32; j += 8)
        t[ty + j][tx] = in[(size_t)(by * 32 + ty + j) * C + bx * 32 + tx];
    __syncthreads();
    #pragma unroll
    for (int j = 0; j < 32; j += 8)
        outp[(size_t)(bx * 32 + ty + j) * R + by * 32 + tx] =
            __float2half_rn(t[tx][ty + j]);
}

// ---------------------------------------------------------------------------
// fp16 GEMM (R14 champion, verbatim): C[M,N] = A[M,K] @ Bt[N,K]^T (+bias).
// 128x128 tile, BK=64, 3-stage cp.async, 256 thr / 8 warps (4m x 2n),
// warp tile 32x64, ldmatrix.x4 fragment loads. Stride 72 halves.
// ---------------------------------------------------------------------------
#define ST_H      72
#define TILE_H    (128 * ST_H)
#define NSTAGE    3
#define GEMM_SMEM (NSTAGE * 2 * TILE_H * 2)    // 110592 bytes

__global__ __launch_bounds__(256, 2) void gemm_h(
    const __half* __restrict__ A, const __half* __restrict__ Bt,
    const float* __restrict__ bias, void* __restrict__ Cout,
    int M, int N, int K, int out_half)
{
    extern __shared__ __align__(16) __half smh[];
    __half* As = smh;                       // [3][128][72]
    __half* Bs = smh + NSTAGE * TILE_H;     // [3][128][72]
    const uint32_t as_a = smem_u32(As);
    const uint32_t bs_a = smem_u32(Bs);

    const int tid  = threadIdx.x;
    const int lane = tid & 31;
    const int wid  = tid >> 5;
    const int wm   = (wid & 3) * 32;
    const int wn   = (wid >> 2) * 64;
    const int bm   = blockIdx.y * 128;
    const int bn   = blockIdx.x * 128;
    const int q    = lane & 3;
    const int g    = lane >> 2;

    const int m8  = lane & 7;
    const int sel = lane >> 3;
    uint32_t a_off[2], b_off[4];
    #pragma unroll
    for (int mt = 0; mt < 2; mt++)
        a_off[mt] = (uint32_t)(((wm + mt * 16 + ((sel & 1) << 3) + m8) * ST_H
                                + ((sel >> 1) << 3)) * 2);
    #pragma unroll
    for (int p = 0; p < 4; p++)
        b_off[p] = (uint32_t)(((wn + ((p << 1) + (sel >> 1)) * 8 + m8) * ST_H
                               + ((sel & 1) << 3)) * 2);

    float acc[2][8][4];
    #pragma unroll
    for (int i = 0; i < 2; i++)
        #pragma unroll
        for (int j = 0; j < 8; j++)
            #pragma unroll
            for (int k = 0; k < 4; k++) acc[i][j][k] = 0.f;

    const int NT = K >> 6;

    #define LOAD_STAGE(kt_)                                                     \
    do {                                                                        \
        const int s_  = (kt_) % NSTAGE;                                         \
        const int k0_ = (kt_) * 64;                                             \
        _Pragma("unroll")                                                       \
        for (int i_ = 0; i_ < 2; i_++) {                                        \
            const int idx_ = tid + i_ * 256;                                    \
            const int row_ = idx_ >> 2;                                         \
            const int c_   = (idx_ & 3) * 16;                                   \
            cp16(as_a + (uint32_t)(s_ * TILE_H + row_ * ST_H + c_) * 2,         \
                 A + (size_t)(bm + row_) * K + k0_ + c_);                       \
            cp16(as_a + (uint32_t)(s_ * TILE_H + row_ * ST_H + c_ + 8) * 2,     \
                 A + (size_t)(bm + row_) * K + k0_ + c_ + 8);                   \
            cp16(bs_a + (uint32_t)(s_ * TILE_H + row_ * ST_H + c_) * 2,         \
                 Bt + (size_t)(bn + row_) * K + k0_ + c_);                      \
            cp16(bs_a + (uint32_t)(s_ * TILE_H + row_ * ST_H + c_ + 8) * 2,     \
                 Bt + (size_t)(bn + row_) * K + k0_ + c_ + 8);                  \
        }                                                                       \
        asm volatile("cp.async.commit_group;" ::: "memory");                    \
    } while (0)

    LOAD_STAGE(0);
    LOAD_STAGE(1);

    for (int kt = 0; kt < NT; kt++) {
        if (kt < NT - 1)
            asm volatile("cp.async.wait_group 1;" ::: "memory");
        else
            asm volatile("cp.async.wait_group 0;" ::: "memory");
        __syncthreads();
        if (kt + 2 < NT) LOAD_STAGE(kt + 2);

        const int st = kt % NSTAGE;
        const uint32_t sa = as_a + (uint32_t)(st * TILE_H) * 2;
        const uint32_t sb = bs_a + (uint32_t)(st * TILE_H) * 2;

        #pragma unroll
        for (int ks = 0; ks < 4; ks++) {
            const uint32_t ko = (uint32_t)(ks * 32);
            unsigned afr[2][4], bfr[8][2];
            ldsm4(afr[0], sa + a_off[0] + ko);
            ldsm4(afr[1], sa + a_off[1] + ko);
            #pragma unroll
            for (int p = 0; p < 4; p++) {
                unsigned t[4];
                ldsm4(t, sb + b_off[p] + ko);
                bfr[2 * p][0] = t[0]; bfr[2 * p][1] = t[1];
                bfr[2 * p + 1][0] = t[2]; bfr[2 * p + 1][1] = t[3];
            }
            #pragma unroll
            for (int mt = 0; mt < 2; mt++)
                #pragma unroll
                for (int nt = 0; nt < 8; nt++)
                    mma_f16(acc[mt][nt], afr[mt], bfr[nt]);
        }
    }

    if (out_half) {
        __half* Ch = (__half*)Cout;
        #pragma unroll
        for (int nt = 0; nt < 8; nt++) {
            const int col = bn + wn + nt * 8 + 2 * q;
            #pragma unroll
            for (int mt = 0; mt < 2; mt++) {
                const int r0 = bm + wm + mt * 16 + g;
                *(__half2*)(Ch + (size_t)r0 * N + col) =
                    __floats2half2_rn(acc[mt][nt][0], acc[mt][nt][1]);
                *(__half2*)(Ch + (size_t)(r0 + 8) * N + col) =
                    __floats2half2_rn(acc[mt][nt][2], acc[mt][nt][3]);
            }
        }
    } else {
        float* Cf = (float*)Cout;
        #pragma unroll
        for (int nt = 0; nt < 8; nt++) {
            const int col = bn + wn + nt * 8 + 2 * q;
            float b0 = 0.f, b1 = 0.f;
            if (bias) { b0 = bias[col]; b1 = bias[col + 1]; }
            #pragma unroll
            for (int mt = 0; mt < 2; mt++) {
                const int r0 = bm + wm + mt * 16 + g;
                *(float2*)(Cf + (size_t)r0 * N + col) =
                    make_float2(acc[mt][nt][0] + b0, acc[mt][nt][1] + b1);
                *(float2*)(Cf + (size_t)(r0 + 8) * N + col) =
                    make_float2(acc[mt][nt][2] + b0, acc[mt][nt][3] + b1);
            }
        }
    }
    #undef LOAD_STAGE
}

// ---------------------------------------------------------------------------
// Window attention: fp16 mma, TWO windows per 256-thread block (8 warps).
// Q/K/V loaded via cp.async into 3 smem planes (V no longer register-held).
// Warp wid: sub = wid>>2 selects window, w4 = wid&3 owns rows 16*w4..16*w4+15.
// P-write -> PV sync is a per-window named barrier (128 threads).
// ---------------------------------------------------------------------------
#define AST      72
#define ATT_PLANE (64 * AST)                 // halves per (mat,win) plane
#define ATT_SMEM (6 * ATT_PLANE * 2)         // 55296 bytes

__global__ __launch_bounds__(256) void window_attn_h(
    const __half* __restrict__ qkv, __half* __restrict__ out)
{
    extern __shared__ __align__(16) __half ash[];
    // plane order: Q0,Q1,K0,K1,V0,V1  (mat*2 + win)
    const uint32_t base_a = smem_u32(ash);

    const int tid  = threadIdx.x;
    const int lane = tid & 31;
    const int wid  = tid >> 5;          // 0..7
    const int sub  = wid >> 2;          // window within pair
    const int w4   = wid & 3;           // row quarter
    const int g    = lane >> 2;
    const int q    = lane & 3;
    const int m8   = lane & 7;
    const int sel  = lane >> 3;

    const int base = blockIdx.x * 2;    // first window index
    const int n0   = base & 63;
    const int h    = (base >> 6) & 7;
    const int b    = base >> 9;

    // Async-load Q,K,V of both windows (12 x 16B per thread).
    #pragma unroll
    for (int i = 0; i < 12; i++) {
        const int pos = i * 256 + tid;      // 0..3071
        const int mat = pos >> 10;          // 0=Q 1=K 2=V
        const int rem = pos & 1023;
        const int win = rem >> 9;
        const int rc  = rem & 511;
        const int row = rc >> 3;            // 0..63
        const int c8  = (rc & 7) * 8;       // halves 0..56
        const size_t tokbase =
            ((size_t)(b * NWIN + n0 + win) * WSZ) * (3 * DIM);
        const __half* src =
            qkv + tokbase + (size_t)row * (3 * DIM) + h * DH + mat * DIM + c8;
        cp16(base_a + (uint32_t)((mat * 2 + win) * ATT_PLANE + row * AST + c8) * 2,
             src);
    }
    asm volatile("cp.async.commit_group;" ::: "memory");
    asm volatile("cp.async.wait_group 0;" ::: "memory");
    __syncthreads();

    const uint32_t qbase = base_a + (uint32_t)((0 + sub) * ATT_PLANE) * 2;
    const uint32_t kbase = base_a + (uint32_t)((2 + sub) * ATT_PLANE) * 2;
    const uint32_t vbase = base_a + (uint32_t)((4 + sub) * ATT_PLANE) * 2;

    const uint32_t aoff =
        (uint32_t)(((w4 * 16 + ((sel & 1) << 3) + m8) * AST + ((sel >> 1) << 3)) * 2);
    uint32_t boff[4], voff[4];
    #pragma unroll
    for (int p = 0; p < 4; p++) {
        boff[p] = (uint32_t)(((((p << 1) + (sel >> 1)) * 8 + m8) * AST
                              + ((sel & 1) << 3)) * 2);
        voff[p] = (uint32_t)(((((sel & 1) << 3) + m8) * AST
                              + ((p << 1) + (sel >> 1)) * 8) * 2);
    }

    // S = Q K^T
    float sacc[8][4];
    #pragma unroll
    for (int nt = 0; nt < 8; nt++)
        #pragma unroll
        for (int j = 0; j < 4; j++) sacc[nt][j] = 0.f;

    #pragma unroll
    for (int ks = 0; ks < 4; ks++) {
        const uint32_t ko = (uint32_t)(ks * 32);
        unsigned a[4], bfr[8][2];
        ldsm4(a, qbase + aoff + ko);
        #pragma unroll
        for (int p = 0; p < 4; p++) {
            unsigned t[4];
            ldsm4(t, kbase + boff[p] + ko);
            bfr[2 * p][0] = t[0]; bfr[2 * p][1] = t[1];
            bfr[2 * p + 1][0] = t[2]; bfr[2 * p + 1][1] = t[3];
        }
        #pragma unroll
        for (int nt = 0; nt < 8; nt++)
            mma_f16(sacc[nt], a, bfr[nt]);
    }

    // Register softmax (rows warp-private)
    const float scale = 0.125f;
    float mx0 = -1e30f, mx1 = -1e30f;
    #pragma unroll
    for (int nt = 0; nt < 8; nt++) {
        #pragma unroll
        for (int j = 0; j < 4; j++) sacc[nt][j] *= scale;
        mx0 = fmaxf(mx0, fmaxf(sacc[nt][0], sacc[nt][1]));
        mx1 = fmaxf(mx1, fmaxf(sacc[nt][2], sacc[nt][3]));
    }
    mx0 = fmaxf(mx0, __shfl_xor_sync(0xffffffffu, mx0, 1));
    mx0 = fmaxf(mx0, __shfl_xor_sync(0xffffffffu, mx0, 2));
    mx1 = fmaxf(mx1, __shfl_xor_sync(0xffffffffu, mx1, 1));
    mx1 = fmaxf(mx1, __shfl_xor_sync(0xffffffffu, mx1, 2));

    float s0 = 0.f, s1 = 0.f;
    #pragma unroll
    for (int nt = 0; nt < 8; nt++) {
        sacc[nt][0] = __expf(sacc[nt][0] - mx0);
        sacc[nt][1] = __expf(sacc[nt][1] - mx0);
        sacc[nt][2] = __expf(sacc[nt][2] - mx1);
        sacc[nt][3] = __expf(sacc[nt][3] - mx1);
        s0 += sacc[nt][0] + sacc[nt][1];
        s1 += sacc[nt][2] + sacc[nt][3];
    }
    s0 += __shfl_xor_sync(0xffffffffu, s0, 1);
    s0 += __shfl_xor_sync(0xffffffffu, s0, 2);
    s1 += __shfl_xor_sync(0xffffffffu, s1, 1);
    s1 += __shfl_xor_sync(0xffffffffu, s1, 2);
    const float inv0 = 1.f / s0, inv1 = 1.f / s1;

    // P -> Q plane (warp-private rows), then per-window named barrier
    {
        __half* Qp = ash + (size_t)(0 + sub) * ATT_PLANE;
        const int r = w4 * 16 + g;
        #pragma unroll
        for (int nt = 0; nt < 8; nt++) {
            const int col = nt * 8 + 2 * q;
            *(__half2*)(Qp + r * AST + col) =
                __floats2half2_rn(sacc[nt][0] * inv0, sacc[nt][1] * inv0);
            *(__half2*)(Qp + (r + 8) * AST + col) =
                __floats2half2_rn(sacc[nt][2] * inv1, sacc[nt][3] * inv1);
        }
    }
    asm volatile("bar.sync %0, 128;" :: "r"(sub + 1) : "memory");

    // O = P V  (V via ldmatrix.trans from its own plane)
    float oacc[8][4];
    #pragma unroll
    for (int nt = 0; nt < 8; nt++)
        #pragma unroll
        for (int j = 0; j < 4; j++) oacc[nt][j] = 0.f;

    #pragma unroll
    for (int ks = 0; ks < 4; ks++) {
        const uint32_t ko  = (uint32_t)(ks * 32);
        const uint32_t kov = (uint32_t)(ks * 16 * AST * 2);
        unsigned a[4], bfr[8][2];
        ldsm4(a, qbase + aoff + ko);
        #pragma unroll
        for (int p = 0; p < 4; p++) {
            unsigned t[4];
            ldsm4t(t, vbase + voff[p] + kov);
            bfr[2 * p][0] = t[0]; bfr[2 * p][1] = t[1];
            bfr[2 * p + 1][0] = t[2]; bfr[2 * p + 1][1] = t[3];
        }
        #pragma unroll
        for (int nt = 0; nt < 8; nt++)
            mma_f16(oacc[nt], a, bfr[nt]);
    }

    // O -> half, [B,H,NW,W,dh] linear layout
    const size_t obase =
        (((size_t)(b * HEADS + h) * NWIN + (n0 + sub)) * WSZ) * DH;
    const int r = w4 * 16 + g;
    #pragma unroll
    for (int nt = 0; nt < 8; nt++) {
        const int col = nt * 8 + 2 * q;
        *(__half2*)(out + obase + (size_t)r * DH + col) =
            __floats2half2_rn(oacc[nt][0], oacc[nt][1]);
        *(__half2*)(out + obase + (size_t)(r + 8) * DH + col) =
            __floats2half2_rn(oacc[nt][2], oacc[nt][3]);
    }
}

// ---------------------------------------------------------------------------
extern "C" void kernel_launch(void* const* d_in, const int* in_sizes, int n_in,
                              void* d_out, int out_size)
{
    const float* x      = (const float*)d_in[0];  // [8,64,64,512]
    const float* w_qkv  = (const float*)d_in[1];  // [512,1536]
    const float* w_proj = (const float*)d_in[2];  // [512,512]
    const float* b_proj = (const float*)d_in[3];  // [512]
    float* out = (float*)d_out;                   // [8,64,64,512]

    __half *xh, *qkvh, *attnh, *wth;
    cudaGetSymbolAddress((void**)&xh,    g_xh);
    cudaGetSymbolAddress((void**)&qkvh,  g_qkvh);
    cudaGetSymbolAddress((void**)&attnh, g_attnh);
    cudaGetSymbolAddress((void**)&wth,   g_wth);
    __half* wqkvT_h  = wth;                            // [1536,512]
    __half* wprojT_h = wth + (size_t)(3 * DIM) * DIM;  // [512,512]

    static bool attr_set = false;
    if (!attr_set) {
        cudaFuncSetAttribute(gemm_h,
                             cudaFuncAttributeMaxDynamicSharedMemorySize, GEMM_SMEM);
        cudaFuncSetAttribute(window_attn_h,
                             cudaFuncAttributeMaxDynamicSharedMemorySize, ATT_SMEM);
        attr_set = true;
    }

    // 0) fused prologue: x -> half; weights -> transposed half (one launch)
    prologue_k<<<16384 + 768 + 256, 256>>>(x, xh, w_qkv, wqkvT_h, w_proj, wprojT_h);

    // 1) qkv = x @ w_qkv (fp16 in, fp16 out)
    {
        dim3 grid((3 * DIM) / 128, NTOK / 128);
        gemm_h<<<grid, 256, GEMM_SMEM>>>(xh, wqkvT_h, nullptr, qkvh,
                                         NTOK, 3 * DIM, DIM, 1);
    }
    // 2) per-window attention (2 windows / block) -> [B,H,NW,W,dh] linear
    {
        window_attn_h<<<BATCH * HEADS * NWIN / 2, 256, ATT_SMEM>>>(qkvh, attnh);
    }
    // 3) out = attn_flat @ w_proj + b_proj (fp16 in, fp32 out)
    {
        dim3 grid(DIM / 128, NTOK / 128);
        gemm_h<<<grid, 256, GEMM_SMEM>>>(attnh, wprojT_h, b_proj, out,
                                         NTOK, DIM, DIM, 0);
    }
}

// round 17
// speedup vs baseline: 1.1163x; 1.0979x over previous
#include <cuda_runtime.h>
#include <cuda_fp16.h>
#include <cstdint>

#define DIM     512
#define HEADS   8
#define DH      64
#define BATCH   8
#define NWIN    64
#define WSZ     64
#define NTOK    (BATCH * NWIN * WSZ)   // 32768

// Scratch (allocation-free rule: __device__ globals)
__device__ __half g_xh[(size_t)NTOK * DIM];                       // 33.5 MB
__device__ __half g_qkvh[(size_t)NTOK * 3 * DIM];                 // 100 MB
__device__ __half g_attnh[(size_t)NTOK * DIM];                    // 33.5 MB
__device__ __half g_wth[(size_t)(3 * DIM) * DIM + DIM * DIM];     // 2 MB (wqkvT, wprojT)

// ---------------------------------------------------------------------------
// helpers
// ---------------------------------------------------------------------------
__device__ __forceinline__ uint32_t smem_u32(const void* p) {
    uint32_t a;
    asm("{ .reg .u64 t; cvta.to.shared.u64 t, %1; cvt.u32.u64 %0, t; }"
        : "=r"(a) : "l"(p));
    return a;
}

__device__ __forceinline__ void cp16(uint32_t dst, const void* src) {
    asm volatile("cp.async.cg.shared.global [%0], [%1], 16;"
                 :: "r"(dst), "l"(src) : "memory");
}

__device__ __forceinline__ void ldsm4(unsigned r[4], uint32_t a) {
    asm volatile("ldmatrix.sync.aligned.m8n8.x4.shared.b16 {%0,%1,%2,%3}, [%4];"
                 : "=r"(r[0]), "=r"(r[1]), "=r"(r[2]), "=r"(r[3]) : "r"(a));
}

__device__ __forceinline__ void ldsm4t(unsigned r[4], uint32_t a) {
    asm volatile("ldmatrix.sync.aligned.m8n8.x4.trans.shared.b16 {%0,%1,%2,%3}, [%4];"
                 : "=r"(r[0]), "=r"(r[1]), "=r"(r[2]), "=r"(r[3]) : "r"(a));
}

__device__ __forceinline__ void mma_f16(float c[4], const unsigned a[4],
                                        const unsigned b[2]) {
    asm volatile(
        "mma.sync.aligned.m16n8k16.row.col.f32.f16.f16.f32 "
        "{%0,%1,%2,%3}, {%4,%5,%6,%7}, {%8,%9}, {%0,%1,%2,%3};"
        : "+f"(c[0]), "+f"(c[1]), "+f"(c[2]), "+f"(c[3])
        : "r"(a[0]), "r"(a[1]), "r"(a[2]), "r"(a[3]), "r"(b[0]), "r"(b[1]));
}

// ---------------------------------------------------------------------------
// Fused prologue (one launch):
//  blocks [0, 16384): x fp32 -> fp16
//  blocks [16384, 17152): transpose+convert w_qkv [512,1536] -> [1536,512] half
//  blocks [17152, 17408): transpose+convert w_proj [512,512] -> [512,512] half
// ---------------------------------------------------------------------------
__global__ __launch_bounds__(256) void prologue_k(
    const float* __restrict__ x, __half* __restrict__ xh,
    const float* __restrict__ w_qkv, __half* __restrict__ wqkvT,
    const float* __restrict__ w_proj, __half* __restrict__ wprojT)
{
    __shared__ float t[32][33];
    const int blk = blockIdx.x;
    const int tid = threadIdx.x;

    if (blk < 16384) {
        const int i = blk * 256 + tid;          // < NTOK*DIM/4
        float4 v = ((const float4*)x)[i];
        __half2* o = (__half2*)(xh + (size_t)i * 4);
        o[0] = __floats2half2_rn(v.x, v.y);
        o[1] = __floats2half2_rn(v.z, v.w);
        return;
    }

    const float* in;
    __half* outp;
    int C, bx, by;
    if (blk < 16384 + 768) {
        in = w_qkv; outp = wqkvT; C = 1536;
        const int bb = blk - 16384;
        bx = bb % 48; by = bb / 48;
    } else {
        in = w_proj; outp = wprojT; C = 512;
        const int bb = blk - 17152;
        bx = bb % 16; by = bb / 16;
    }
    const int R = 512;
    const int tx = tid & 31, ty = tid >> 5;     // 32 x 8
    #pragma unroll
    for (int j = 0; j < 32; j += 8)
        t[ty + j][tx] = in[(size_t)(by * 32 + ty + j) * C + bx * 32 + tx];
    __syncthreads();
    #pragma unroll
    for (int j = 0; j < 32; j += 8)
        outp[(size_t)(bx * 32 + ty + j) * R + by * 32 + tx] =
            __float2half_rn(t[tx][ty + j]);
}

// ---------------------------------------------------------------------------
// fp16 GEMM (R14 mainloop + smem-staged coalesced epilogue, K templated):
// C[M,N] = A[M,K] @ Bt[N,K]^T (+bias). 128x128 tile, BK=64, 3-stage cp.async,
// 256 thr / 8 warps (4m x 2n), warp tile 32x64, ldmatrix.x4 fragment loads.
// ---------------------------------------------------------------------------
#define ST_H      72
#define TILE_H    (128 * ST_H)
#define NSTAGE    3
#define GEMM_SMEM (NSTAGE * 2 * TILE_H * 2)    // 110592 bytes

template<int KK, int OUT_HALF>
__global__ __launch_bounds__(256, 2) void gemm_h(
    const __half* __restrict__ A, const __half* __restrict__ Bt,
    const float* __restrict__ bias, void* __restrict__ Cout,
    int M, int N)
{
    extern __shared__ __align__(16) __half smh[];
    __half* As = smh;                       // [3][128][72]
    __half* Bs = smh + NSTAGE * TILE_H;     // [3][128][72]
    const uint32_t as_a = smem_u32(As);
    const uint32_t bs_a = smem_u32(Bs);

    const int tid  = threadIdx.x;
    const int lane = tid & 31;
    const int wid  = tid >> 5;
    const int wm   = (wid & 3) * 32;
    const int wn   = (wid >> 2) * 64;
    const int bm   = blockIdx.y * 128;
    const int bn   = blockIdx.x * 128;
    const int q    = lane & 3;
    const int g    = lane >> 2;

    const int m8  = lane & 7;
    const int sel = lane >> 3;
    uint32_t a_off[2], b_off[4];
    #pragma unroll
    for (int mt = 0; mt < 2; mt++)
        a_off[mt] = (uint32_t)(((wm + mt * 16 + ((sel & 1) << 3) + m8) * ST_H
                                + ((sel >> 1) << 3)) * 2);
    #pragma unroll
    for (int p = 0; p < 4; p++)
        b_off[p] = (uint32_t)(((wn + ((p << 1) + (sel >> 1)) * 8 + m8) * ST_H
                               + ((sel & 1) << 3)) * 2);

    float acc[2][8][4];
    #pragma unroll
    for (int i = 0; i < 2; i++)
        #pragma unroll
        for (int j = 0; j < 8; j++)
            #pragma unroll
            for (int k = 0; k < 4; k++) acc[i][j][k] = 0.f;

    constexpr int NT = KK >> 6;

    #define LOAD_STAGE(kt_)                                                     \
    do {                                                                        \
        const int s_  = (kt_) % NSTAGE;                                         \
        const int k0_ = (kt_) * 64;                                             \
        _Pragma("unroll")                                                       \
        for (int i_ = 0; i_ < 2; i_++) {                                        \
            const int idx_ = tid + i_ * 256;                                    \
            const int row_ = idx_ >> 2;                                         \
            const int c_   = (idx_ & 3) * 16;                                   \
            cp16(as_a + (uint32_t)(s_ * TILE_H + row_ * ST_H + c_) * 2,         \
                 A + (size_t)(bm + row_) * KK + k0_ + c_);                      \
            cp16(as_a + (uint32_t)(s_ * TILE_H + row_ * ST_H + c_ + 8) * 2,     \
                 A + (size_t)(bm + row_) * KK + k0_ + c_ + 8);                  \
            cp16(bs_a + (uint32_t)(s_ * TILE_H + row_ * ST_H + c_) * 2,         \
                 Bt + (size_t)(bn + row_) * KK + k0_ + c_);                     \
            cp16(bs_a + (uint32_t)(s_ * TILE_H + row_ * ST_H + c_ + 8) * 2,     \
                 Bt + (size_t)(bn + row_) * KK + k0_ + c_ + 8);                 \
        }                                                                       \
        asm volatile("cp.async.commit_group;" ::: "memory");                    \
    } while (0)

    LOAD_STAGE(0);
    LOAD_STAGE(1);

    #pragma unroll
    for (int kt = 0; kt < NT; kt++) {
        if (kt < NT - 1)
            asm volatile("cp.async.wait_group 1;" ::: "memory");
        else
            asm volatile("cp.async.wait_group 0;" ::: "memory");
        __syncthreads();
        if (kt + 2 < NT) LOAD_STAGE(kt + 2);

        const int st = kt % NSTAGE;
        const uint32_t sa = as_a + (uint32_t)(st * TILE_H) * 2;
        const uint32_t sb = bs_a + (uint32_t)(st * TILE_H) * 2;

        #pragma unroll
        for (int ks = 0; ks < 4; ks++) {
            const uint32_t ko = (uint32_t)(ks * 32);
            unsigned afr[2][4], bfr[8][2];
            ldsm4(afr[0], sa + a_off[0] + ko);
            ldsm4(afr[1], sa + a_off[1] + ko);
            #pragma unroll
            for (int p = 0; p < 4; p++) {
                unsigned t[4];
                ldsm4(t, sb + b_off[p] + ko);
                bfr[2 * p][0] = t[0]; bfr[2 * p][1] = t[1];
                bfr[2 * p + 1][0] = t[2]; bfr[2 * p + 1][1] = t[3];
            }
            #pragma unroll
            for (int mt = 0; mt < 2; mt++)
                #pragma unroll
                for (int nt = 0; nt < 8; nt++)
                    mma_f16(acc[mt][nt], afr[mt], bfr[nt]);
        }
    }
    #undef LOAD_STAGE

    // ---- Epilogue: stage C tile in (now dead) pipeline smem, then store
    // fully-coalesced 16B chunks. ----
    __syncthreads();   // mainloop smem reads complete everywhere

    if (OUT_HALF) {
        // half tile 128 x 136 (stride pad): STS banks = 4g+q, conflict-free.
        __half* stg = smh;
        constexpr int SR = 136;
        #pragma unroll
        for (int nt = 0; nt < 8; nt++) {
            const int col = wn + nt * 8 + 2 * q;
            #pragma unroll
            for (int mt = 0; mt < 2; mt++) {
                const int r0 = wm + mt * 16 + g;
                *(__half2*)&stg[r0 * SR + col] =
                    __floats2half2_rn(acc[mt][nt][0], acc[mt][nt][1]);
                *(__half2*)&stg[(r0 + 8) * SR + col] =
                    __floats2half2_rn(acc[mt][nt][2], acc[mt][nt][3]);
            }
        }
        __syncthreads();
        __half* Ch = (__half*)Cout;
        #pragma unroll
        for (int i = tid; i < 2048; i += 256) {      // 128 rows x 16 chunks
            const int row = i >> 4;
            const int c8  = (i & 15) * 8;
            *(uint4*)(Ch + (size_t)(bm + row) * N + bn + c8) =
                *(const uint4*)&stg[row * SR + c8];
        }
    } else {
        // fp32 tile 128 x 132 (66 KB <= 108 KB smem).
        float* stg = (float*)smh;
        constexpr int SR = 132;
        #pragma unroll
        for (int nt = 0; nt < 8; nt++) {
            const int col = wn + nt * 8 + 2 * q;
            #pragma unroll
            for (int mt = 0; mt < 2; mt++) {
                const int r0 = wm + mt * 16 + g;
                stg[r0 * SR + col]           = acc[mt][nt][0];
                stg[r0 * SR + col + 1]       = acc[mt][nt][1];
                stg[(r0 + 8) * SR + col]     = acc[mt][nt][2];
                stg[(r0 + 8) * SR + col + 1] = acc[mt][nt][3];
            }
        }
        __syncthreads();
        float* Cf = (float*)Cout;
        #pragma unroll
        for (int i = tid; i < 4096; i += 256) {      // 128 rows x 32 chunks
            const int row = i >> 5;
            const int c4  = (i & 31) * 4;
            float4 v = *(const float4*)&stg[row * SR + c4];
            if (bias) {
                float4 bv = *(const float4*)(bias + bn + c4);
                v.x += bv.x; v.y += bv.y; v.z += bv.z; v.w += bv.w;
            }
            *(float4*)(Cf + (size_t)(bm + row) * N + bn + c4) = v;
        }
    }
}

// ---------------------------------------------------------------------------
// Window attention (R16 champion, unchanged): fp16 mma, TWO windows per
// 256-thread block, Q/K/V via cp.async into 3 smem planes, named barriers.
// ---------------------------------------------------------------------------
#define AST      72
#define ATT_PLANE (64 * AST)
#define ATT_SMEM (6 * ATT_PLANE * 2)         // 55296 bytes

__global__ __launch_bounds__(256) void window_attn_h(
    const __half* __restrict__ qkv, __half* __restrict__ out)
{
    extern __shared__ __align__(16) __half ash[];
    const uint32_t base_a = smem_u32(ash);

    const int tid  = threadIdx.x;
    const int lane = tid & 31;
    const int wid  = tid >> 5;
    const int sub  = wid >> 2;
    const int w4   = wid & 3;
    const int g    = lane >> 2;
    const int q    = lane & 3;
    const int m8   = lane & 7;
    const int sel  = lane >> 3;

    const int base = blockIdx.x * 2;
    const int n0   = base & 63;
    const int h    = (base >> 6) & 7;
    const int b    = base >> 9;

    #pragma unroll
    for (int i = 0; i < 12; i++) {
        const int pos = i * 256 + tid;
        const int mat = pos >> 10;
        const int rem = pos & 1023;
        const int win = rem >> 9;
        const int rc  = rem & 511;
        const int row = rc >> 3;
        const int c8  = (rc & 7) * 8;
        const size_t tokbase =
            ((size_t)(b * NWIN + n0 + win) * WSZ) * (3 * DIM);
        const __half* src =
            qkv + tokbase + (size_t)row * (3 * DIM) + h * DH + mat * DIM + c8;
        cp16(base_a + (uint32_t)((mat * 2 + win) * ATT_PLANE + row * AST + c8) * 2,
             src);
    }
    asm volatile("cp.async.commit_group;" ::: "memory");
    asm volatile("cp.async.wait_group 0;" ::: "memory");
    __syncthreads();

    const uint32_t qbase = base_a + (uint32_t)((0 + sub) * ATT_PLANE) * 2;
    const uint32_t kbase = base_a + (uint32_t)((2 + sub) * ATT_PLANE) * 2;
    const uint32_t vbase = base_a + (uint32_t)((4 + sub) * ATT_PLANE) * 2;

    const uint32_t aoff =
        (uint32_t)(((w4 * 16 + ((sel & 1) << 3) + m8) * AST + ((sel >> 1) << 3)) * 2);
    uint32_t boff[4], voff[4];
    #pragma unroll
    for (int p = 0; p < 4; p++) {
        boff[p] = (uint32_t)(((((p << 1) + (sel >> 1)) * 8 + m8) * AST
                              + ((sel & 1) << 3)) * 2);
        voff[p] = (uint32_t)(((((sel & 1) << 3) + m8) * AST
                              + ((p << 1) + (sel >> 1)) * 8) * 2);
    }

    float sacc[8][4];
    #pragma unroll
    for (int nt = 0; nt < 8; nt++)
        #pragma unroll
        for (int j = 0; j < 4; j++) sacc[nt][j] = 0.f;

    #pragma unroll
    for (int ks = 0; ks < 4; ks++) {
        const uint32_t ko = (uint32_t)(ks * 32);
        unsigned a[4], bfr[8][2];
        ldsm4(a, qbase + aoff + ko);
        #pragma unroll
        for (int p = 0; p < 4; p++) {
            unsigned t[4];
            ldsm4(t, kbase + boff[p] + ko);
            bfr[2 * p][0] = t[0]; bfr[2 * p][1] = t[1];
            bfr[2 * p + 1][0] = t[2]; bfr[2 * p + 1][1] = t[3];
        }
        #pragma unroll
        for (int nt = 0; nt < 8; nt++)
            mma_f16(sacc[nt], a, bfr[nt]);
    }

    const float scale = 0.125f;
    float mx0 = -1e30f, mx1 = -1e30f;
    #pragma unroll
    for (int nt = 0; nt < 8; nt++) {
        #pragma unroll
        for (int j = 0; j < 4; j++) sacc[nt][j] *= scale;
        mx0 = fmaxf(mx0, fmaxf(sacc[nt][0], sacc[nt][1]));
        mx1 = fmaxf(mx1, fmaxf(sacc[nt][2], sacc[nt][3]));
    }
    mx0 = fmaxf(mx0, __shfl_xor_sync(0xffffffffu, mx0, 1));
    mx0 = fmaxf(mx0, __shfl_xor_sync(0xffffffffu, mx0, 2));
    mx1 = fmaxf(mx1, __shfl_xor_sync(0xffffffffu, mx1, 1));
    mx1 = fmaxf(mx1, __shfl_xor_sync(0xffffffffu, mx1, 2));

    float s0 = 0.f, s1 = 0.f;
    #pragma unroll
    for (int nt = 0; nt < 8; nt++) {
        sacc[nt][0] = __expf(sacc[nt][0] - mx0);
        sacc[nt][1] = __expf(sacc[nt][1] - mx0);
        sacc[nt][2] = __expf(sacc[nt][2] - mx1);
        sacc[nt][3] = __expf(sacc[nt][3] - mx1);
        s0 += sacc[nt][0] + sacc[nt][1];
        s1 += sacc[nt][2] + sacc[nt][3];
    }
    s0 += __shfl_xor_sync(0xffffffffu, s0, 1);
    s0 += __shfl_xor_sync(0xffffffffu, s0, 2);
    s1 += __shfl_xor_sync(0xffffffffu, s1, 1);
    s1 += __shfl_xor_sync(0xffffffffu, s1, 2);
    const float inv0 = 1.f / s0, inv1 = 1.f / s1;

    {
        __half* Qp = ash + (size_t)(0 + sub) * ATT_PLANE;
        const int r = w4 * 16 + g;
        #pragma unroll
        for (int nt = 0; nt < 8; nt++) {
            const int col = nt * 8 + 2 * q;
            *(__half2*)(Qp + r * AST + col) =
                __floats2half2_rn(sacc[nt][0] * inv0, sacc[nt][1] * inv0);
            *(__half2*)(Qp + (r + 8) * AST + col) =
                __floats2half2_rn(sacc[nt][2] * inv1, sacc[nt][3] * inv1);
        }
    }
    asm volatile("bar.sync %0, 128;" :: "r"(sub + 1) : "memory");

    float oacc[8][4];
    #pragma unroll
    for (int nt = 0; nt < 8; nt++)
        #pragma unroll
        for (int j = 0; j < 4; j++) oacc[nt][j] = 0.f;

    #pragma unroll
    for (int ks = 0; ks < 4; ks++) {
        const uint32_t ko  = (uint32_t)(ks * 32);
        const uint32_t kov = (uint32_t)(ks * 16 * AST * 2);
        unsigned a[4], bfr[8][2];
        ldsm4(a, qbase + aoff + ko);
        #pragma unroll
        for (int p = 0; p < 4; p++) {
            unsigned t[4];
            ldsm4t(t, vbase + voff[p] + kov);
            bfr[2 * p][0] = t[0]; bfr[2 * p][1] = t[1];
            bfr[2 * p + 1][0] = t[2]; bfr[2 * p + 1][1] = t[3];
        }
        #pragma unroll
        for (int nt = 0; nt < 8; nt++)
            mma_f16(oacc[nt], a, bfr[nt]);
    }

    const size_t obase =
        (((size_t)(b * HEADS + h) * NWIN + (n0 + sub)) * WSZ) * DH;
    const int r = w4 * 16 + g;
    #pragma unroll
    for (int nt = 0; nt < 8; nt++) {
        const int col = nt * 8 + 2 * q;
        *(__half2*)(out + obase + (size_t)r * DH + col) =
            __floats2half2_rn(oacc[nt][0], oacc[nt][1]);
        *(__half2*)(out + obase + (size_t)(r + 8) * DH + col) =
            __floats2half2_rn(oacc[nt][2], oacc[nt][3]);
    }
}

// ---------------------------------------------------------------------------
extern "C" void kernel_launch(void* const* d_in, const int* in_sizes, int n_in,
                              void* d_out, int out_size)
{
    const float* x      = (const float*)d_in[0];  // [8,64,64,512]
    const float* w_qkv  = (const float*)d_in[1];  // [512,1536]
    const float* w_proj = (const float*)d_in[2];  // [512,512]
    const float* b_proj = (const float*)d_in[3];  // [512]
    float* out = (float*)d_out;                   // [8,64,64,512]

    __half *xh, *qkvh, *attnh, *wth;
    cudaGetSymbolAddress((void**)&xh,    g_xh);
    cudaGetSymbolAddress((void**)&qkvh,  g_qkvh);
    cudaGetSymbolAddress((void**)&attnh, g_attnh);
    cudaGetSymbolAddress((void**)&wth,   g_wth);
    __half* wqkvT_h  = wth;                            // [1536,512]
    __half* wprojT_h = wth + (size_t)(3 * DIM) * DIM;  // [512,512]

    static bool attr_set = false;
    if (!attr_set) {
        cudaFuncSetAttribute(gemm_h<512, 1>,
                             cudaFuncAttributeMaxDynamicSharedMemorySize, GEMM_SMEM);
        cudaFuncSetAttribute(gemm_h<512, 0>,
                             cudaFuncAttributeMaxDynamicSharedMemorySize, GEMM_SMEM);
        cudaFuncSetAttribute(window_attn_h,
                             cudaFuncAttributeMaxDynamicSharedMemorySize, ATT_SMEM);
        attr_set = true;
    }

    // 0) fused prologue: x -> half; weights -> transposed half (one launch)
    prologue_k<<<16384 + 768 + 256, 256>>>(x, xh, w_qkv, wqkvT_h, w_proj, wprojT_h);

    // 1) qkv = x @ w_qkv (fp16 in, fp16 out)
    {
        dim3 grid((3 * DIM) / 128, NTOK / 128);
        gemm_h<512, 1><<<grid, 256, GEMM_SMEM>>>(xh, wqkvT_h, nullptr, qkvh,
                                                 NTOK, 3 * DIM);
    }
    // 2) per-window attention (2 windows / block) -> [B,H,NW,W,dh] linear
    {
        window_attn_h<<<BATCH * HEADS * NWIN / 2, 256, ATT_SMEM>>>(qkvh, attnh);
    }
    // 3) out = attn_flat @ w_proj + b_proj (fp16 in, fp32 out)
    {
        dim3 grid(DIM / 128, NTOK / 128);
        gemm_h<512, 0><<<grid, 256, GEMM_SMEM>>>(attnh, wprojT_h, b_proj, out,
                                                 NTOK, DIM);
    }
}